// round 14
// baseline (speedup 1.0000x reference)
#include <cuda_runtime.h>
#include <cstdint>
#include <math.h>

// Binary MLP B=16384, D=H=1024, C=10 — all-popc path.
// Bit-packed XOR + balanced CSA(q=16); BN+sign folded to integer threshold.
// 4 rows/iteration for deep ILP; 128-thread blocks; separate fast prep kernels.

#define NB       16384
#define KW       32
#define HN       1024
#define ROWS_PB  64
#define GRP_PB   4
#define THREADS  128

__device__ unsigned g_act[2][NB * KW];     // ping-pong packed activations
__device__ unsigned g_wt[3][KW * HN];      // packed hidden weights [word j][neuron n]
__device__ unsigned g_w4[10 * KW];         // packed output weights
__device__ int2     g_thri[3 * HN];        // (thr, neg) per neuron per layer

__device__ __forceinline__ unsigned lop3_96(unsigned a, unsigned b, unsigned c) { // a^b^c
    unsigned r;
    asm("lop3.b32 %0, %1, %2, %3, 0x96;" : "=r"(r) : "r"(a), "r"(b), "r"(c));
    return r;
}
__device__ __forceinline__ unsigned lop3_e8(unsigned a, unsigned b, unsigned c) { // maj
    unsigned r;
    asm("lop3.b32 %0, %1, %2, %3, 0xE8;" : "=r"(r) : "r"(a), "r"(b), "r"(c));
    return r;
}
#define FA(a, b, c, s, cy) { s = lop3_96(a, b, c); cy = lop3_e8(a, b, c); }

// exact 1024-bit popcount of x[0..31]: 9 naive + 23-word CSA (16 FAs, 7 popcs)
__device__ __forceinline__ int count1024(const unsigned* __restrict__ x) {
    int a0 = __popc(x[0]) + __popc(x[1]) + __popc(x[2]);
    int a1 = __popc(x[3]) + __popc(x[4]) + __popc(x[5]);
    int a2 = __popc(x[6]) + __popc(x[7]) + __popc(x[8]);

    unsigned s0,c0,s1,c1,s2,c2,s3,c3,s4,c4,s5,c5,s6,c6;
    FA(x[9],  x[10], x[11], s0, c0);
    FA(x[12], x[13], x[14], s1, c1);
    FA(x[15], x[16], x[17], s2, c2);
    FA(x[18], x[19], x[20], s3, c3);
    FA(x[21], x[22], x[23], s4, c4);
    FA(x[24], x[25], x[26], s5, c5);
    FA(x[27], x[28], x[29], s6, c6);
    unsigned u0,d0,u1,d1,u2,d2,u3,d3;
    FA(s0, s1, s2,       u0, d0);
    FA(s3, s4, s5,       u1, d1);
    FA(s6, x[30], x[31], u2, d2);
    FA(u0, u1, u2,       u3, d3);
    unsigned e0,f0,e1,f1,e2,f2,e3,f3,e4,f4;
    FA(c0, c1, c2, e0, f0);
    FA(c3, c4, c5, e1, f1);
    FA(c6, d0, d1, e2, f2);
    FA(e0, e1, e2, e3, f3);
    FA(e3, d2, d3, e4, f4);

    int F = (__popc(f0) + __popc(f1) + __popc(f2)) + (__popc(f3) + __popc(f4));
    return (a0 + a1 + a2) + __popc(u3) + 2 * __popc(e4) + 4 * F;
}

// ======================= prep kernels (R1/R8 proven-fast forms) =======================
__global__ void pack_x_kernel(const float* __restrict__ x) {
    int t = blockIdx.x * blockDim.x + threadIdx.x;     // NB*1024 threads
    unsigned bit = (x[t] >= 0.5f) ? 1u : 0u;            // sign(2x-1) >= 0
    unsigned word = __ballot_sync(0xffffffffu, bit);
    if ((t & 31) == 0) g_act[0][t >> 5] = word;
}

__global__ void pack_w_kernel(const float* __restrict__ W, int widx) {
    int t = blockIdx.x * blockDim.x + threadIdx.x;     // 32*1024 threads (1/word)
    if (t >= KW * HN) return;
    int n = t & (HN - 1), j = t >> 10;
    const float4* p = reinterpret_cast<const float4*>(W + (size_t)n * 1024 + j * 32);
    unsigned bits = 0;
#pragma unroll
    for (int i = 0; i < 8; i++) {
        float4 v = p[i];
        bits |= (v.x >= 0.0f ? 1u : 0u) << (4 * i + 0);
        bits |= (v.y >= 0.0f ? 1u : 0u) << (4 * i + 1);
        bits |= (v.z >= 0.0f ? 1u : 0u) << (4 * i + 2);
        bits |= (v.w >= 0.0f ? 1u : 0u) << (4 * i + 3);
    }
    g_wt[widx][j * HN + n] = bits;
}

__global__ void pack_w4_kernel(const float* __restrict__ W4) {
    int t = blockIdx.x * blockDim.x + threadIdx.x;     // 10*1024 threads
    if (t >= 10 * 1024) return;
    unsigned bit = (W4[t] >= 0.0f) ? 1u : 0u;
    unsigned word = __ballot_sync(0xffffffffu, bit);
    if ((t & 31) == 0) g_w4[t >> 5] = word;
}

// exact integer thresholds: bit = ((P <= thr) ? 1 : 0) ^ neg
__global__ void thr_kernel(const float* __restrict__ g, const float* __restrict__ b,
                           const float* __restrict__ m, const float* __restrict__ v,
                           int2* __restrict__ out) {
    int n = blockIdx.x * blockDim.x + threadIdx.x;
    if (n >= HN) return;
    double sc = (double)g[n] / sqrt((double)v[n] + 1e-5);
    int thr; int neg;
    if (sc > 0.0) {
        double T = (1024.0 - (double)m[n] + (double)b[n] / sc) * 0.5;
        T = fmin(fmax(T, -2.0e9), 2.0e9);
        thr = (int)floor(T); neg = 0;
    } else if (sc < 0.0) {
        double T = (1024.0 - (double)m[n] + (double)b[n] / sc) * 0.5;
        T = fmin(fmax(T, -2.0e9), 2.0e9);
        thr = (int)ceil(T) - 1; neg = 1;
    } else {
        thr = ((double)b[n] >= 0.0) ? 0x7fffffff : (-0x7fffffff - 1); neg = 0;
    }
    out[n] = make_int2(thr, neg);
}

// ======================= hidden layer =======================
// grid (NB/ROWS_PB, HN/(GRP_PB*32)) = (256, 8); 4 warps/block, one group each;
// 4 rows per inner iteration for deep ILP.
__global__ void __launch_bounds__(THREADS)
layer_kernel(int src, int dst, int widx, const int2* __restrict__ thrv) {
    __shared__ uint4 sh_a[ROWS_PB][8];

    const int tid  = threadIdx.x;
    const int lane = tid & 31;
    const int wid  = tid >> 5;
    const int row0 = blockIdx.x * ROWS_PB;
    const int grp  = blockIdx.y * GRP_PB + wid;
    const int n    = grp * 32 + lane;

    {   // stage A tile: 64 rows x 32 words = 512 uint4
        const uint4* asrc = reinterpret_cast<const uint4*>(&g_act[src][(size_t)row0 * KW]);
        uint4* adst = &sh_a[0][0];
#pragma unroll
        for (int t = 0; t < ROWS_PB * 8 / THREADS; t++)
            adst[tid + t * THREADS] = asrc[tid + t * THREADS];
    }

    unsigned w[KW];
    const unsigned* wt = &g_wt[widx][0];
#pragma unroll
    for (int j = 0; j < KW; j++) w[j] = wt[j * HN + n];

    const int2 tn  = thrv[n];
    const int  thr = tn.x;
    const unsigned neg = (unsigned)tn.y;
    __syncthreads();

    unsigned* out = &g_act[dst][0];
    for (int r = 0; r < ROWS_PB; r += 4) {
        int P[4];
#pragma unroll
        for (int k = 0; k < 4; k++) {
            unsigned x[32];
#pragma unroll
            for (int i = 0; i < 8; i++) {
                uint4 a = sh_a[r + k][i];
                x[4 * i + 0] = a.x ^ w[4 * i + 0];
                x[4 * i + 1] = a.y ^ w[4 * i + 1];
                x[4 * i + 2] = a.z ^ w[4 * i + 2];
                x[4 * i + 3] = a.w ^ w[4 * i + 3];
            }
            P[k] = count1024(x);
        }
#pragma unroll
        for (int k = 0; k < 4; k++) {
            unsigned bit = ((P[k] <= thr) ? 1u : 0u) ^ neg;
            unsigned wb = __ballot_sync(0xffffffffu, bit != 0u);
            if (lane == 0) out[(size_t)(row0 + r + k) * KW + grp] = wb;
        }
    }
}

// ======================= final layer + TensorNorm =======================
__global__ void final_kernel(const float* __restrict__ tnw, const float* __restrict__ tnb,
                             const float* __restrict__ tnm, const float* __restrict__ tnv,
                             float* __restrict__ out) {
    __shared__ unsigned sw[10 * KW];
    const int tid = threadIdx.x;
    for (int i = tid; i < 10 * KW; i += blockDim.x) sw[i] = g_w4[i];
    __syncthreads();

    int row = blockIdx.x * blockDim.x + tid;
    if (row >= NB) return;

    uint4 a[8];
    const uint4* p = reinterpret_cast<const uint4*>(&g_act[1][(size_t)row * KW]);
#pragma unroll
    for (int i = 0; i < 8; i++) a[i] = p[i];

    float rs = (float)(1.0 / sqrt((double)tnv[0] + 1e-4));
    float wq = tnw[0], bq = tnb[0], mq = tnm[0];

#pragma unroll
    for (int c = 0; c < 10; c++) {
        int P = 0;
#pragma unroll
        for (int i = 0; i < 8; i++) {
            P += __popc(a[i].x ^ sw[c * KW + 4 * i + 0]);
            P += __popc(a[i].y ^ sw[c * KW + 4 * i + 1]);
            P += __popc(a[i].z ^ sw[c * KW + 4 * i + 2]);
            P += __popc(a[i].w ^ sw[c * KW + 4 * i + 3]);
        }
        float s = (float)(1024 - 2 * P);
        out[(size_t)row * 10 + c] = ((s - mq) * rs) * wq + bq;
    }
}

// ======================= launch =======================
extern "C" void kernel_launch(void* const* d_in, const int* in_sizes, int n_in,
                              void* d_out, int out_size) {
    const float* x  = (const float*)d_in[0];
    const float* W1 = (const float*)d_in[1];
    const float* W2 = (const float*)d_in[2];
    const float* W3 = (const float*)d_in[3];
    const float* W4 = (const float*)d_in[4];
    const float* g1 = (const float*)d_in[5],  *b1 = (const float*)d_in[6];
    const float* m1 = (const float*)d_in[7],  *v1 = (const float*)d_in[8];
    const float* g2 = (const float*)d_in[9],  *b2 = (const float*)d_in[10];
    const float* m2 = (const float*)d_in[11], *v2 = (const float*)d_in[12];
    const float* g3 = (const float*)d_in[13], *b3 = (const float*)d_in[14];
    const float* m3 = (const float*)d_in[15], *v3 = (const float*)d_in[16];
    const float* tnw = (const float*)d_in[17], *tnb = (const float*)d_in[18];
    const float* tnm = (const float*)d_in[19], *tnv = (const float*)d_in[20];
    float* out = (float*)d_out;

    void* pt;
    cudaGetSymbolAddress(&pt, g_thri);
    int2* tv = (int2*)pt;

    pack_x_kernel<<<NB * 1024 / 256, 256>>>(x);
    pack_w_kernel<<<(KW * HN + 255) / 256, 256>>>(W1, 0);
    pack_w_kernel<<<(KW * HN + 255) / 256, 256>>>(W2, 1);
    pack_w_kernel<<<(KW * HN + 255) / 256, 256>>>(W3, 2);
    thr_kernel<<<4, 256>>>(g1, b1, m1, v1, tv);
    thr_kernel<<<4, 256>>>(g2, b2, m2, v2, tv + 1024);
    thr_kernel<<<4, 256>>>(g3, b3, m3, v3, tv + 2048);
    pack_w4_kernel<<<40, 256>>>(W4);

    dim3 lgrid(NB / ROWS_PB, HN / (GRP_PB * 32));    // (256, 8)
    layer_kernel<<<lgrid, THREADS>>>(0, 1, 0, tv);
    layer_kernel<<<lgrid, THREADS>>>(1, 0, 1, tv + 1024);
    layer_kernel<<<lgrid, THREADS>>>(0, 1, 2, tv + 2048);

    final_kernel<<<NB / 256, 256>>>(tnw, tnb, tnm, tnv, out);
}

// round 15
// speedup vs baseline: 1.0836x; 1.0836x over previous
#include <cuda_runtime.h>
#include <cstdint>
#include <math.h>

// Binary MLP B=16384, D=H=1024, C=10 — all-popc path.
// Layer body = R12 measured-best (128-thr, 2-row arrays, regs 64, alu-bound).
// ROWS_PB=32 for wave-quantization relief; fused-parallel weight packing.

#define NB       16384
#define KW       32
#define HN       1024
#define ROWS_PB  32
#define GRP_PB   4
#define THREADS  128

__device__ unsigned g_act[2][NB * KW];     // ping-pong packed activations
__device__ unsigned g_wt[3][KW * HN];      // packed hidden weights [word j][neuron n]
__device__ unsigned g_w4[10 * KW];         // packed output weights
__device__ int2     g_thri[3 * HN];        // (thr, neg) per neuron per layer

__device__ __forceinline__ unsigned lop3_96(unsigned a, unsigned b, unsigned c) { // a^b^c
    unsigned r;
    asm("lop3.b32 %0, %1, %2, %3, 0x96;" : "=r"(r) : "r"(a), "r"(b), "r"(c));
    return r;
}
__device__ __forceinline__ unsigned lop3_e8(unsigned a, unsigned b, unsigned c) { // maj
    unsigned r;
    asm("lop3.b32 %0, %1, %2, %3, 0xE8;" : "=r"(r) : "r"(a), "r"(b), "r"(c));
    return r;
}
#define FA(a, b, c, s, cy) { s = lop3_96(a, b, c); cy = lop3_e8(a, b, c); }

// exact 1024-bit popcount of x[0..31]: 9 naive + 23-word CSA (16 FAs, 7 popcs)
__device__ __forceinline__ int count1024(const unsigned* __restrict__ x) {
    int a0 = __popc(x[0]) + __popc(x[1]) + __popc(x[2]);
    int a1 = __popc(x[3]) + __popc(x[4]) + __popc(x[5]);
    int a2 = __popc(x[6]) + __popc(x[7]) + __popc(x[8]);

    unsigned s0,c0,s1,c1,s2,c2,s3,c3,s4,c4,s5,c5,s6,c6;
    FA(x[9],  x[10], x[11], s0, c0);
    FA(x[12], x[13], x[14], s1, c1);
    FA(x[15], x[16], x[17], s2, c2);
    FA(x[18], x[19], x[20], s3, c3);
    FA(x[21], x[22], x[23], s4, c4);
    FA(x[24], x[25], x[26], s5, c5);
    FA(x[27], x[28], x[29], s6, c6);
    unsigned u0,d0,u1,d1,u2,d2,u3,d3;
    FA(s0, s1, s2,       u0, d0);
    FA(s3, s4, s5,       u1, d1);
    FA(s6, x[30], x[31], u2, d2);
    FA(u0, u1, u2,       u3, d3);
    unsigned e0,f0,e1,f1,e2,f2,e3,f3,e4,f4;
    FA(c0, c1, c2, e0, f0);
    FA(c3, c4, c5, e1, f1);
    FA(c6, d0, d1, e2, f2);
    FA(e0, e1, e2, e3, f3);
    FA(e3, d2, d3, e4, f4);

    int F = (__popc(f0) + __popc(f1) + __popc(f2)) + (__popc(f3) + __popc(f4));
    return (a0 + a1 + a2) + __popc(u3) + 2 * __popc(e4) + 4 * F;
}

// ======================= prep kernels =======================
__global__ void pack_x_kernel(const float* __restrict__ x) {
    int t = blockIdx.x * blockDim.x + threadIdx.x;     // NB*1024 threads
    unsigned bit = (x[t] >= 0.5f) ? 1u : 0u;            // sign(2x-1) >= 0
    unsigned word = __ballot_sync(0xffffffffu, bit);
    if ((t & 31) == 0) g_act[0][t >> 5] = word;
}

// all three hidden weight matrices in one launch: blockIdx.y selects layer
__global__ void pack_w3_kernel(const float* __restrict__ W1,
                               const float* __restrict__ W2,
                               const float* __restrict__ W3) {
    int t = blockIdx.x * blockDim.x + threadIdx.x;     // 32*1024 per layer
    if (t >= KW * HN) return;
    int widx = blockIdx.y;
    const float* W = (widx == 0) ? W1 : (widx == 1) ? W2 : W3;
    int n = t & (HN - 1), j = t >> 10;
    const float4* p = reinterpret_cast<const float4*>(W + (size_t)n * 1024 + j * 32);
    unsigned bits = 0;
#pragma unroll
    for (int i = 0; i < 8; i++) {
        float4 v = p[i];
        bits |= (v.x >= 0.0f ? 1u : 0u) << (4 * i + 0);
        bits |= (v.y >= 0.0f ? 1u : 0u) << (4 * i + 1);
        bits |= (v.z >= 0.0f ? 1u : 0u) << (4 * i + 2);
        bits |= (v.w >= 0.0f ? 1u : 0u) << (4 * i + 3);
    }
    g_wt[widx][j * HN + n] = bits;
}

__global__ void pack_w4_kernel(const float* __restrict__ W4) {
    int t = blockIdx.x * blockDim.x + threadIdx.x;     // 10*1024 threads
    if (t >= 10 * 1024) return;
    unsigned bit = (W4[t] >= 0.0f) ? 1u : 0u;
    unsigned word = __ballot_sync(0xffffffffu, bit);
    if ((t & 31) == 0) g_w4[t >> 5] = word;
}

// fused thresholds for 3 layers: bit = ((P <= thr) ? 1 : 0) ^ neg
__global__ void thr_all_kernel(const float* __restrict__ g1, const float* __restrict__ b1,
                               const float* __restrict__ m1, const float* __restrict__ v1,
                               const float* __restrict__ g2, const float* __restrict__ b2,
                               const float* __restrict__ m2, const float* __restrict__ v2,
                               const float* __restrict__ g3, const float* __restrict__ b3,
                               const float* __restrict__ m3, const float* __restrict__ v3) {
    int t = blockIdx.x * blockDim.x + threadIdx.x;
    if (t >= 3 * HN) return;
    int l = t >> 10, n = t & (HN - 1);
    const float* g = (l == 0) ? g1 : (l == 1) ? g2 : g3;
    const float* b = (l == 0) ? b1 : (l == 1) ? b2 : b3;
    const float* m = (l == 0) ? m1 : (l == 1) ? m2 : m3;
    const float* v = (l == 0) ? v1 : (l == 1) ? v2 : v3;

    double sc = (double)g[n] / sqrt((double)v[n] + 1e-5);
    int thr; int neg;
    if (sc > 0.0) {
        double T = (1024.0 - (double)m[n] + (double)b[n] / sc) * 0.5;
        T = fmin(fmax(T, -2.0e9), 2.0e9);
        thr = (int)floor(T); neg = 0;
    } else if (sc < 0.0) {
        double T = (1024.0 - (double)m[n] + (double)b[n] / sc) * 0.5;
        T = fmin(fmax(T, -2.0e9), 2.0e9);
        thr = (int)ceil(T) - 1; neg = 1;
    } else {
        thr = ((double)b[n] >= 0.0) ? 0x7fffffff : (-0x7fffffff - 1); neg = 0;
    }
    g_thri[t] = make_int2(thr, neg);
}

// ======================= hidden layer (R12 measured-best body) =======================
// grid (NB/ROWS_PB, HN/(GRP_PB*32)) = (512, 8); 4 warps, one 32-neuron group each;
// 2 rows per inner iteration (explicit arrays — proven schedule, regs 64).
__global__ void __launch_bounds__(THREADS)
layer_kernel(int src, int dst, int widx, const int2* __restrict__ thrv) {
    __shared__ uint4 sh_a[ROWS_PB][8];

    const int tid  = threadIdx.x;
    const int lane = tid & 31;
    const int wid  = tid >> 5;
    const int row0 = blockIdx.x * ROWS_PB;
    const int grp  = blockIdx.y * GRP_PB + wid;
    const int n    = grp * 32 + lane;

    {   // stage A tile: 32 rows x 32 words = 256 uint4
        const uint4* asrc = reinterpret_cast<const uint4*>(&g_act[src][(size_t)row0 * KW]);
        uint4* adst = &sh_a[0][0];
#pragma unroll
        for (int t = 0; t < ROWS_PB * 8 / THREADS; t++)
            adst[tid + t * THREADS] = asrc[tid + t * THREADS];
    }

    unsigned w[KW];
    const unsigned* wt = &g_wt[widx][0];
#pragma unroll
    for (int j = 0; j < KW; j++) w[j] = wt[j * HN + n];

    const int2 tn  = thrv[n];
    const int  thr = tn.x;
    const unsigned neg = (unsigned)tn.y;
    __syncthreads();

    unsigned* out = &g_act[dst][0];
    for (int r = 0; r < ROWS_PB; r += 2) {
        unsigned x0[32], x1[32];
#pragma unroll
        for (int i = 0; i < 8; i++) {
            uint4 a0 = sh_a[r][i];
            uint4 a1 = sh_a[r + 1][i];
            x0[4 * i + 0] = a0.x ^ w[4 * i + 0];
            x0[4 * i + 1] = a0.y ^ w[4 * i + 1];
            x0[4 * i + 2] = a0.z ^ w[4 * i + 2];
            x0[4 * i + 3] = a0.w ^ w[4 * i + 3];
            x1[4 * i + 0] = a1.x ^ w[4 * i + 0];
            x1[4 * i + 1] = a1.y ^ w[4 * i + 1];
            x1[4 * i + 2] = a1.z ^ w[4 * i + 2];
            x1[4 * i + 3] = a1.w ^ w[4 * i + 3];
        }
        int P0 = count1024(x0);
        int P1 = count1024(x1);

        unsigned bit0 = ((P0 <= thr) ? 1u : 0u) ^ neg;
        unsigned bit1 = ((P1 <= thr) ? 1u : 0u) ^ neg;
        unsigned wb0 = __ballot_sync(0xffffffffu, bit0 != 0u);
        unsigned wb1 = __ballot_sync(0xffffffffu, bit1 != 0u);
        if (lane == 0) {
            out[(size_t)(row0 + r)     * KW + grp] = wb0;
            out[(size_t)(row0 + r + 1) * KW + grp] = wb1;
        }
    }
}

// ======================= final layer + TensorNorm =======================
__global__ void final_kernel(const float* __restrict__ tnw, const float* __restrict__ tnb,
                             const float* __restrict__ tnm, const float* __restrict__ tnv,
                             float* __restrict__ out) {
    __shared__ unsigned sw[10 * KW];
    const int tid = threadIdx.x;
    for (int i = tid; i < 10 * KW; i += blockDim.x) sw[i] = g_w4[i];
    __syncthreads();

    int row = blockIdx.x * blockDim.x + tid;
    if (row >= NB) return;

    uint4 a[8];
    const uint4* p = reinterpret_cast<const uint4*>(&g_act[1][(size_t)row * KW]);
#pragma unroll
    for (int i = 0; i < 8; i++) a[i] = p[i];

    float rs = (float)(1.0 / sqrt((double)tnv[0] + 1e-4));
    float wq = tnw[0], bq = tnb[0], mq = tnm[0];

#pragma unroll
    for (int c = 0; c < 10; c++) {
        int P = 0;
#pragma unroll
        for (int i = 0; i < 8; i++) {
            P += __popc(a[i].x ^ sw[c * KW + 4 * i + 0]);
            P += __popc(a[i].y ^ sw[c * KW + 4 * i + 1]);
            P += __popc(a[i].z ^ sw[c * KW + 4 * i + 2]);
            P += __popc(a[i].w ^ sw[c * KW + 4 * i + 3]);
        }
        float s = (float)(1024 - 2 * P);
        out[(size_t)row * 10 + c] = ((s - mq) * rs) * wq + bq;
    }
}

// ======================= launch =======================
extern "C" void kernel_launch(void* const* d_in, const int* in_sizes, int n_in,
                              void* d_out, int out_size) {
    const float* x  = (const float*)d_in[0];
    const float* W1 = (const float*)d_in[1];
    const float* W2 = (const float*)d_in[2];
    const float* W3 = (const float*)d_in[3];
    const float* W4 = (const float*)d_in[4];
    const float* g1 = (const float*)d_in[5],  *b1 = (const float*)d_in[6];
    const float* m1 = (const float*)d_in[7],  *v1 = (const float*)d_in[8];
    const float* g2 = (const float*)d_in[9],  *b2 = (const float*)d_in[10];
    const float* m2 = (const float*)d_in[11], *v2 = (const float*)d_in[12];
    const float* g3 = (const float*)d_in[13], *b3 = (const float*)d_in[14];
    const float* m3 = (const float*)d_in[15], *v3 = (const float*)d_in[16];
    const float* tnw = (const float*)d_in[17], *tnb = (const float*)d_in[18];
    const float* tnm = (const float*)d_in[19], *tnv = (const float*)d_in[20];
    float* out = (float*)d_out;

    void* pt;
    cudaGetSymbolAddress(&pt, g_thri);
    int2* tv = (int2*)pt;

    pack_x_kernel<<<NB * 1024 / 256, 256>>>(x);
    dim3 wgrid((KW * HN + 255) / 256, 3);
    pack_w3_kernel<<<wgrid, 256>>>(W1, W2, W3);
    thr_all_kernel<<<12, 256>>>(g1, b1, m1, v1, g2, b2, m2, v2, g3, b3, m3, v3);
    pack_w4_kernel<<<40, 256>>>(W4);

    dim3 lgrid(NB / ROWS_PB, HN / (GRP_PB * 32));    // (512, 8)
    layer_kernel<<<lgrid, THREADS>>>(0, 1, 0, tv);
    layer_kernel<<<lgrid, THREADS>>>(1, 0, 1, tv + 1024);
    layer_kernel<<<lgrid, THREADS>>>(0, 1, 2, tv + 2048);

    final_kernel<<<NB / 256, 256>>>(tnw, tnb, tnm, tnv, out);
}